// round 15
// baseline (speedup 1.0000x reference)
#include <cuda_runtime.h>
#include <cuda_bf16.h>

// GraphSAGE inference — single launch, fully warp-autonomous.
//   agg0[b] = (mean_n [e_n | mean_nn e_nn]) @ W1  (fc1 linear => commutes w/ mean)
// One warp = one batch row end-to-end: gather 250+10 embeds -> xbar -> fc1 -> fc0.
// No weight pre-pack (j-packed f32x2 uses raw row-major W), no __syncthreads.
// Shapes fixed: B=4096, N0=10, N1=25, D=64, H=128.

#define B_     4096
#define N0_    10
#define N1_    25
#define D_     64
#define GB     8            // rows per block = warps per block
#define NBLK   (B_ / GB)    // 512 blocks
#define SNW    264          // ints per warp id buffer (250 n1 + 10 n0 + pad)

// ---- packed-fp32 helpers (f32x2 only via PTX) ----
__device__ __forceinline__ unsigned long long pack2(float a, float b) {
    unsigned long long r;
    asm("mov.b64 %0, {%1, %2};" : "=l"(r) : "f"(a), "f"(b));
    return r;
}
__device__ __forceinline__ void unpack2(unsigned long long v, float& a, float& b) {
    asm("mov.b64 {%0, %1}, %2;" : "=f"(a), "=f"(b) : "l"(v));
}
__device__ __forceinline__ void ffma2(unsigned long long& d,
                                      unsigned long long a, unsigned long long b) {
    asm("fma.rn.f32x2 %0, %1, %2, %0;" : "+l"(d) : "l"(a), "l"(b));
}

__global__ void __launch_bounds__(256, 4) sage_v5(
    const int*   __restrict__ inputs,
    const int*   __restrict__ neigh0,
    const int*   __restrict__ neigh1,
    const float* __restrict__ embed,
    const float* __restrict__ W1,
    const float* __restrict__ W0,
    const float* __restrict__ b0,
    float*       __restrict__ out)
{
    __shared__ int snbuf[GB * SNW];                  // per-warp id staging
    __shared__ __align__(16) float xbar[GB][128];    // [sum(e_n)/10 | sum(e_nn)/250]
    __shared__ __align__(16) float xb[GB][192];      // [e_v | agg0]

    const int t    = threadIdx.x;
    const int w    = t >> 5;                         // warp = local batch row
    const int lane = t & 31;
    const int c4   = lane & 15;                      // float4 column slot
    const int hh   = lane >> 4;                      // even/odd id half
    const int row  = blockIdx.x * GB + w;            // global batch row
    const float4* eb = (const float4*)embed;
    int* sn = &snbuf[w * SNW];

    // ---- stage this warp's ids (warp-private) ----
    for (int i = lane; i < N0_ * N1_; i += 32)
        sn[i] = __ldg(neigh1 + (size_t)row * (N0_ * N1_) + i);
    if (lane < N0_)
        sn[250 + lane] = __ldg(neigh0 + row * N0_ + lane);
    __syncwarp();

    // ---- gather-sum: half hh sums ids hh, hh+2, ... (125 of 250) ----
    float4 a1 = make_float4(0.f, 0.f, 0.f, 0.f);
    {
        const int* sni = sn + hh;
        #pragma unroll 1
        for (int it = 0; it < 25; it++) {            // 25 batches x 5 loads
            const int base = it * 10;
            const float4 v0 = __ldg(eb + (size_t)sni[base + 0] * 16 + c4);
            const float4 v1 = __ldg(eb + (size_t)sni[base + 2] * 16 + c4);
            const float4 v2 = __ldg(eb + (size_t)sni[base + 4] * 16 + c4);
            const float4 v3 = __ldg(eb + (size_t)sni[base + 6] * 16 + c4);
            const float4 v4 = __ldg(eb + (size_t)sni[base + 8] * 16 + c4);
            a1.x += v0.x + v1.x + v2.x + v3.x + v4.x;
            a1.y += v0.y + v1.y + v2.y + v3.y + v4.y;
            a1.z += v0.z + v1.z + v2.z + v3.z + v4.z;
            a1.w += v0.w + v1.w + v2.w + v3.w + v4.w;
        }
    }
    // neigh0: 5 ids per half
    float4 a0;
    {
        const int* sn0 = sn + 250 + hh;
        const float4 u0 = __ldg(eb + (size_t)sn0[0] * 16 + c4);
        const float4 u1 = __ldg(eb + (size_t)sn0[2] * 16 + c4);
        const float4 u2 = __ldg(eb + (size_t)sn0[4] * 16 + c4);
        const float4 u3 = __ldg(eb + (size_t)sn0[6] * 16 + c4);
        const float4 u4 = __ldg(eb + (size_t)sn0[8] * 16 + c4);
        a0 = make_float4(u0.x + u1.x + u2.x + u3.x + u4.x,
                         u0.y + u1.y + u2.y + u3.y + u4.y,
                         u0.z + u1.z + u2.z + u3.z + u4.z,
                         u0.w + u1.w + u2.w + u3.w + u4.w);
    }
    // e_v row (upper half loads it while lower half reduces)
    float4 ev = make_float4(0.f, 0.f, 0.f, 0.f);
    if (hh == 1)
        ev = __ldg(eb + (size_t)__ldg(inputs + row) * 16 + c4);

    // ---- combine halves via shfl.xor 16 (warp-local) ----
    a1.x += __shfl_xor_sync(0xffffffffu, a1.x, 16);
    a1.y += __shfl_xor_sync(0xffffffffu, a1.y, 16);
    a1.z += __shfl_xor_sync(0xffffffffu, a1.z, 16);
    a1.w += __shfl_xor_sync(0xffffffffu, a1.w, 16);
    a0.x += __shfl_xor_sync(0xffffffffu, a0.x, 16);
    a0.y += __shfl_xor_sync(0xffffffffu, a0.y, 16);
    a0.z += __shfl_xor_sync(0xffffffffu, a0.z, 16);
    a0.w += __shfl_xor_sync(0xffffffffu, a0.w, 16);

    if (hh == 0) {
        const float s1 = 1.f / 250.f, s0 = 1.f / 10.f;
        *(float4*)&xbar[w][64 + 4 * c4] =
            make_float4(a1.x * s1, a1.y * s1, a1.z * s1, a1.w * s1);
        *(float4*)&xbar[w][4 * c4] =
            make_float4(a0.x * s0, a0.y * s0, a0.z * s0, a0.w * s0);
    } else {
        *(float4*)&xb[w][4 * c4] = ev;
    }
    __syncwarp();       // warp-private data; no block barrier anywhere

    // ---- fc1: lane computes agg0 cols 4*lane..4*lane+3 of its row ----
    {
        unsigned long long a01 = 0ull, a23 = 0ull;
        #pragma unroll 4
        for (int k4 = 0; k4 < 32; k4++) {
            const float4 xv = *(const float4*)&xbar[w][4 * k4];   // LDS.128
            const float xs[4] = {xv.x, xv.y, xv.z, xv.w};
            #pragma unroll
            for (int kk = 0; kk < 4; kk++) {
                const int k = 4 * k4 + kk;
                const ulonglong2 wv =
                    *(const ulonglong2*)&W1[(size_t)k * 128 + 4 * lane]; // raw W!
                const unsigned long long xx = pack2(xs[kk], xs[kk]);
                ffma2(a01, xx, wv.x);
                ffma2(a23, xx, wv.y);
            }
        }
        float f0, f1, f2, f3;
        unpack2(a01, f0, f1);
        unpack2(a23, f2, f3);
        *(float4*)&xb[w][64 + 4 * lane] = make_float4(f0, f1, f2, f3);
    }
    __syncwarp();

    // ---- fc0 + sigmoid: lane emits out[row][4*lane..4*lane+3] ----
    {
        unsigned long long a01 = 0ull, a23 = 0ull;
        #pragma unroll 4
        for (int k4 = 0; k4 < 48; k4++) {
            const float4 xv = *(const float4*)&xb[w][4 * k4];     // LDS.128
            const float xs[4] = {xv.x, xv.y, xv.z, xv.w};
            #pragma unroll
            for (int kk = 0; kk < 4; kk++) {
                const int k = 4 * k4 + kk;
                const ulonglong2 wv =
                    *(const ulonglong2*)&W0[(size_t)k * 128 + 4 * lane];
                const unsigned long long xx = pack2(xs[kk], xs[kk]);
                ffma2(a01, xx, wv.x);
                ffma2(a23, xx, wv.y);
            }
        }
        const float4 bj = *(const float4*)&b0[4 * lane];
        float f0, f1, f2, f3;
        unpack2(a01, f0, f1);
        unpack2(a23, f2, f3);
        float4 r;
        r.x = 1.f / (1.f + __expf(-(f0 + bj.x)));
        r.y = 1.f / (1.f + __expf(-(f1 + bj.y)));
        r.z = 1.f / (1.f + __expf(-(f2 + bj.z)));
        r.w = 1.f / (1.f + __expf(-(f3 + bj.w)));
        *(float4*)&out[(size_t)row * 128 + 4 * lane] = r;
    }
}

extern "C" void kernel_launch(void* const* d_in, const int* in_sizes, int n_in,
                              void* d_out, int out_size)
{
    // Bind inputs by element count (all distinct):
    //   inputs 4096 | neigh0 40960 | neigh1 1024000 | embed 64000064
    //   W1 16384 | W0 24576 | b0 128
    const int *inputs = nullptr, *neigh0 = nullptr, *neigh1 = nullptr;
    const float *embed = nullptr, *W1 = nullptr, *W0 = nullptr, *b0 = nullptr;
    for (int i = 0; i < n_in; i++) {
        switch (in_sizes[i]) {
            case 4096:     inputs = (const int*)  d_in[i]; break;
            case 40960:    neigh0 = (const int*)  d_in[i]; break;
            case 1024000:  neigh1 = (const int*)  d_in[i]; break;
            case 64000064: embed  = (const float*)d_in[i]; break;
            case 16384:    W1     = (const float*)d_in[i]; break;
            case 24576:    W0     = (const float*)d_in[i]; break;
            case 128:      b0     = (const float*)d_in[i]; break;
        }
    }

    sage_v5<<<NBLK, 256>>>(inputs, neigh0, neigh1, embed, W1, W0, b0,
                           (float*)d_out);
}

// round 17
// speedup vs baseline: 1.1534x; 1.1534x over previous
#include <cuda_runtime.h>
#include <cuda_bf16.h>

// GraphSAGE inference — single launch, warp-per-row gather + j-threaded fc (raw W).
//   agg0[b] = (mean_n [e_n | mean_nn e_nn]) @ W1  (fc1 linear => commutes w/ mean)
// Shapes fixed: B=4096, N0=10, N1=25, D=64, H=128.

#define B_     4096
#define N0_    10
#define N1_    25
#define D_     64
#define GB     8            // rows per block = warps per block
#define NBLK   (B_ / GB)    // 512 blocks
#define SNW    264          // ints per warp id buffer (250 n1 + 10 n0 + pad)

// ---- packed-fp32 helpers (f32x2 only via PTX) ----
__device__ __forceinline__ unsigned long long pack2(float a, float b) {
    unsigned long long r;
    asm("mov.b64 %0, {%1, %2};" : "=l"(r) : "f"(a), "f"(b));
    return r;
}
__device__ __forceinline__ void unpack2(unsigned long long v, float& a, float& b) {
    asm("mov.b64 {%0, %1}, %2;" : "=f"(a), "=f"(b) : "l"(v));
}
__device__ __forceinline__ void ffma2(unsigned long long& d,
                                      unsigned long long a, unsigned long long b) {
    asm("fma.rn.f32x2 %0, %1, %2, %0;" : "+l"(d) : "l"(a), "l"(b));
}

__global__ void __launch_bounds__(256, 4) sage_v6(
    const int*   __restrict__ inputs,
    const int*   __restrict__ neigh0,
    const int*   __restrict__ neigh1,
    const float* __restrict__ embed,
    const float* __restrict__ W1,
    const float* __restrict__ W0,
    const float* __restrict__ b0,
    float*       __restrict__ out)
{
    __shared__ int snbuf[GB * SNW];                  // per-warp id staging
    __shared__ __align__(16) float xbar[GB][128];    // [sum(e_n)/10 | sum(e_nn)/250]
    __shared__ __align__(16) float xb[GB][192];      // [e_v | agg0]

    const int t    = threadIdx.x;
    const int w    = t >> 5;                         // warp = local batch row
    const int lane = t & 31;
    const int c4   = lane & 15;                      // float4 column slot
    const int hh   = lane >> 4;                      // even/odd id half
    const int row  = blockIdx.x * GB + w;            // global batch row
    const float4* eb = (const float4*)embed;
    int* sn = &snbuf[w * SNW];

    // ---- stage this warp's ids (warp-private) ----
    for (int i = lane; i < N0_ * N1_; i += 32)
        sn[i] = __ldg(neigh1 + (size_t)row * (N0_ * N1_) + i);
    if (lane < N0_)
        sn[250 + lane] = __ldg(neigh0 + row * N0_ + lane);
    __syncwarp();

    // ---- gather-sum: half hh sums ids hh, hh+2, ... (125 of 250) ----
    float4 a1 = make_float4(0.f, 0.f, 0.f, 0.f);
    {
        const int* sni = sn + hh;
        #pragma unroll 1
        for (int it = 0; it < 12; it++) {            // 12 batches x 10 loads
            const int base = it * 20;
            float4 v[10];
            #pragma unroll
            for (int u = 0; u < 10; u++)
                v[u] = __ldg(eb + (size_t)sni[base + 2 * u] * 16 + c4);
            #pragma unroll
            for (int u = 0; u < 10; u++) {
                a1.x += v[u].x; a1.y += v[u].y; a1.z += v[u].z; a1.w += v[u].w;
            }
        }
        // tail: ids 240..249 (5 per half)
        {
            const int base = 240;
            float4 v[5];
            #pragma unroll
            for (int u = 0; u < 5; u++)
                v[u] = __ldg(eb + (size_t)sni[base + 2 * u] * 16 + c4);
            #pragma unroll
            for (int u = 0; u < 5; u++) {
                a1.x += v[u].x; a1.y += v[u].y; a1.z += v[u].z; a1.w += v[u].w;
            }
        }
    }
    // neigh0: 5 ids per half
    float4 a0;
    {
        const int* sn0 = sn + 250 + hh;
        const float4 u0 = __ldg(eb + (size_t)sn0[0] * 16 + c4);
        const float4 u1 = __ldg(eb + (size_t)sn0[2] * 16 + c4);
        const float4 u2 = __ldg(eb + (size_t)sn0[4] * 16 + c4);
        const float4 u3 = __ldg(eb + (size_t)sn0[6] * 16 + c4);
        const float4 u4 = __ldg(eb + (size_t)sn0[8] * 16 + c4);
        a0 = make_float4(u0.x + u1.x + u2.x + u3.x + u4.x,
                         u0.y + u1.y + u2.y + u3.y + u4.y,
                         u0.z + u1.z + u2.z + u3.z + u4.z,
                         u0.w + u1.w + u2.w + u3.w + u4.w);
    }
    // e_v row (upper half loads it while lower half reduces)
    float4 ev = make_float4(0.f, 0.f, 0.f, 0.f);
    if (hh == 1)
        ev = __ldg(eb + (size_t)__ldg(inputs + row) * 16 + c4);

    // ---- combine halves via shfl.xor 16 (warp-local) ----
    a1.x += __shfl_xor_sync(0xffffffffu, a1.x, 16);
    a1.y += __shfl_xor_sync(0xffffffffu, a1.y, 16);
    a1.z += __shfl_xor_sync(0xffffffffu, a1.z, 16);
    a1.w += __shfl_xor_sync(0xffffffffu, a1.w, 16);
    a0.x += __shfl_xor_sync(0xffffffffu, a0.x, 16);
    a0.y += __shfl_xor_sync(0xffffffffu, a0.y, 16);
    a0.z += __shfl_xor_sync(0xffffffffu, a0.z, 16);
    a0.w += __shfl_xor_sync(0xffffffffu, a0.w, 16);

    if (hh == 0) {
        const float s1 = 1.f / 250.f, s0 = 1.f / 10.f;
        *(float4*)&xbar[w][64 + 4 * c4] =
            make_float4(a1.x * s1, a1.y * s1, a1.z * s1, a1.w * s1);
        *(float4*)&xbar[w][4 * c4] =
            make_float4(a0.x * s0, a0.y * s0, a0.z * s0, a0.w * s0);
    } else {
        *(float4*)&xb[w][4 * c4] = ev;
    }
    __syncthreads();

    const int j  = t & 127;                          // output column
    const int h2 = t >> 7;                           // rows h2*4 .. h2*4+3

    // ---- fc1: agg0[r] = xbar[r] @ W1, raw row-major W (no pre-pack) ----
    {
        unsigned long long acc[4] = {0ull, 0ull, 0ull, 0ull};
        #pragma unroll 4
        for (int k2 = 0; k2 < 64; k2++) {
            const unsigned long long wv =
                pack2(__ldg(&W1[(size_t)(2 * k2)     * 128 + j]),   // LDG.32 x2,
                      __ldg(&W1[(size_t)(2 * k2 + 1) * 128 + j]));  // L1/L2-hot
            #pragma unroll
            for (int r = 0; r < 4; r++) {
                const unsigned long long xv =
                    *(const unsigned long long*)&xbar[h2 * 4 + r][2 * k2];  // LDS.64
                ffma2(acc[r], xv, wv);
            }
        }
        #pragma unroll
        for (int r = 0; r < 4; r++) {
            float a, b; unpack2(acc[r], a, b);
            xb[h2 * 4 + r][64 + j] = a + b;
        }
    }
    __syncthreads();

    // ---- fc0 + sigmoid ----
    {
        unsigned long long acc[4] = {0ull, 0ull, 0ull, 0ull};
        #pragma unroll 4
        for (int k2 = 0; k2 < 96; k2++) {
            const unsigned long long wv =
                pack2(__ldg(&W0[(size_t)(2 * k2)     * 128 + j]),
                      __ldg(&W0[(size_t)(2 * k2 + 1) * 128 + j]));
            #pragma unroll
            for (int r = 0; r < 4; r++) {
                const unsigned long long xv =
                    *(const unsigned long long*)&xb[h2 * 4 + r][2 * k2];
                ffma2(acc[r], xv, wv);
            }
        }
        const float bj = __ldg(b0 + j);
        const int bb = blockIdx.x * GB;
        #pragma unroll
        for (int r = 0; r < 4; r++) {
            float a, b; unpack2(acc[r], a, b);
            const float hv = a + b + bj;
            out[(size_t)(bb + h2 * 4 + r) * 128 + j] = 1.f / (1.f + __expf(-hv));
        }
    }
}

extern "C" void kernel_launch(void* const* d_in, const int* in_sizes, int n_in,
                              void* d_out, int out_size)
{
    // Bind inputs by element count (all distinct):
    //   inputs 4096 | neigh0 40960 | neigh1 1024000 | embed 64000064
    //   W1 16384 | W0 24576 | b0 128
    const int *inputs = nullptr, *neigh0 = nullptr, *neigh1 = nullptr;
    const float *embed = nullptr, *W1 = nullptr, *W0 = nullptr, *b0 = nullptr;
    for (int i = 0; i < n_in; i++) {
        switch (in_sizes[i]) {
            case 4096:     inputs = (const int*)  d_in[i]; break;
            case 40960:    neigh0 = (const int*)  d_in[i]; break;
            case 1024000:  neigh1 = (const int*)  d_in[i]; break;
            case 64000064: embed  = (const float*)d_in[i]; break;
            case 16384:    W1     = (const float*)d_in[i]; break;
            case 24576:    W0     = (const float*)d_in[i]; break;
            case 128:      b0     = (const float*)d_in[i]; break;
        }
    }

    sage_v6<<<NBLK, 256>>>(inputs, neigh0, neigh1, embed, W1, W0, b0,
                           (float*)d_out);
}